// round 9
// baseline (speedup 1.0000x reference)
#include <cuda_runtime.h>
#include <cuda_bf16.h>

#define R_EARTH  6371000.0f
#define DEG2RADF 0.017453292519943295f
#define DT_SEC   600.0f
#define NSTEPS   48

#define TILE 32

// Scratch ping-pong buffer (B*H*W = 8*1024*1024 floats = 32 MB) — static device
// global, NOT an allocation.
__device__ float g_scratch[8u * 1024u * 1024u];

// Per-row reciprocal dx terms (H <= 4096) + dy scalars.
__device__ float g_inv_dx[4096];
__device__ float g_inv_2dx[4096];
__device__ float g_inv_dy;
__device__ float g_inv_2dy;

__global__ void setup_kernel(const float* __restrict__ lat,
                             const float* __restrict__ lon, int H) {
    float dlat = lat[1] - lat[0];
    float dlon = lon[1] - lon[0];
    float dy = R_EARTH * DEG2RADF * dlat;
    if (blockIdx.x == 0 && threadIdx.x == 0) {
        g_inv_dy  = 1.0f / dy;
        g_inv_2dy = 0.5f / dy;
    }
    float dx0 = R_EARTH * DEG2RADF * dlon;
    for (int i = blockIdx.x * blockDim.x + threadIdx.x; i < H;
         i += gridDim.x * blockDim.x) {
        float dx = dx0 * cosf(lat[i] * DEG2RADF);
        g_inv_dx[i]  = 1.0f / dx;
        g_inv_2dx[i] = 0.5f / dx;
    }
}

// One fused timestep: Tn = mask * conv3x3( T + DT * F(T) ), with
// F = -(ug*dT/dx + vg*dT/dy) * mask, one-sided derivatives at domain edges,
// zero padding for the convolution at domain edges.
__global__ __launch_bounds__(256)
void step_kernel(const float* __restrict__ src_ext, int src_is_scratch,
                 float* __restrict__ dst_ext, int dst_is_scratch,
                 const float* __restrict__ ug, const float* __restrict__ vg,
                 const float* __restrict__ mask, int H, int W) {
    const float* src = src_is_scratch ? g_scratch : src_ext;
    float*       dst = dst_is_scratch ? g_scratch : dst_ext;

    __shared__ float sT[TILE + 4][TILE + 5];   // halo-2 tile of T  (36 x 37)
    __shared__ float sA[TILE + 2][TILE + 3];   // halo-1 advected   (34 x 35)

    const int b   = blockIdx.z;
    const int gy0 = blockIdx.y * TILE;
    const int gx0 = blockIdx.x * TILE;
    const size_t plane = (size_t)H * (size_t)W;
    const float* Tb  = src + (size_t)b * plane;
    const float* ugb = ug  + (size_t)b * plane;
    const float* vgb = vg  + (size_t)b * plane;

    const int tid = threadIdx.y * 32 + threadIdx.x;   // blockDim = (32, 8)

    // ---- Load T tile with halo 2 (out-of-domain -> 0, never consumed) ----
    #pragma unroll
    for (int idx = tid; idx < 36 * 36; idx += 256) {
        int ly = idx / 36, lx = idx % 36;
        int gy = gy0 - 2 + ly, gx = gx0 - 2 + lx;
        float v = 0.0f;
        if (gy >= 0 && gy < H && gx >= 0 && gx < W)
            v = Tb[(size_t)gy * W + gx];
        sT[ly][lx] = v;
    }
    __syncthreads();

    const float inv_dy  = g_inv_dy;
    const float inv_2dy = g_inv_2dy;

    // ---- Advected field A = T + DT*F on halo-1 region; 0 outside domain ----
    #pragma unroll
    for (int idx = tid; idx < 34 * 34; idx += 256) {
        int ay = idx / 34, ax = idx % 34;
        int gy = gy0 - 1 + ay, gx = gx0 - 1 + ax;
        float a = 0.0f;
        if (gy >= 0 && gy < H && gx >= 0 && gx < W) {
            int ty = ay + 1, tx = ax + 1;
            float c = sT[ty][tx];
            float dTdy;
            if (gy == 0)            dTdy = (sT[ty + 1][tx] - c) * inv_dy;
            else if (gy == H - 1)   dTdy = (c - sT[ty - 1][tx]) * inv_dy;
            else                    dTdy = (sT[ty + 1][tx] - sT[ty - 1][tx]) * inv_2dy;
            float dTdx;
            if (gx == 0)            dTdx = (sT[ty][tx + 1] - c) * g_inv_dx[gy];
            else if (gx == W - 1)   dTdx = (c - sT[ty][tx - 1]) * g_inv_dx[gy];
            else                    dTdx = (sT[ty][tx + 1] - sT[ty][tx - 1]) * g_inv_2dx[gy];
            size_t g = (size_t)gy * W + gx;
            float F = -(ugb[g] * dTdx + vgb[g] * dTdy) * mask[g];
            a = fmaf(DT_SEC, F, c);
        }
        sA[ay][ax] = a;
    }
    __syncthreads();

    // ---- 3x3 binomial smooth + mask, 32x32 outputs (4 rows per thread) ----
    const int ox = threadIdx.x;
    const int gx = gx0 + ox;
    if (gx < W) {
        #pragma unroll
        for (int r = 0; r < 4; r++) {
            int oy = threadIdx.y * 4 + r;
            int gy = gy0 + oy;
            if (gy >= H) break;
            float s =
                  sA[oy    ][ox] + 2.0f * sA[oy    ][ox + 1] + sA[oy    ][ox + 2]
         + 2.0f * sA[oy + 1][ox] + 4.0f * sA[oy + 1][ox + 1] + 2.0f * sA[oy + 1][ox + 2]
         +        sA[oy + 2][ox] + 2.0f * sA[oy + 2][ox + 1] + sA[oy + 2][ox + 2];
            s *= 0.0625f;
            dst[((size_t)b * H + gy) * (size_t)W + gx] =
                s * mask[(size_t)gy * W + gx];
        }
    }
}

extern "C" void kernel_launch(void* const* d_in, const int* in_sizes, int n_in,
                              void* d_out, int out_size) {
    const float* T    = (const float*)d_in[0];
    const float* ug   = (const float*)d_in[1];
    const float* vg   = (const float*)d_in[2];
    const float* lat  = (const float*)d_in[3];
    const float* lon  = (const float*)d_in[4];
    const float* mask = (const float*)d_in[5];
    float* out = (float*)d_out;

    const int H = in_sizes[3];
    const int W = in_sizes[4];
    const int B = in_sizes[0] / (H * W);

    setup_kernel<<<(H + 255) / 256, 256>>>(lat, lon, H);

    dim3 block(32, 8);
    dim3 grid((W + TILE - 1) / TILE, (H + TILE - 1) / TILE, B);

    // Ping-pong so that the final step (s = NSTEPS-1) writes d_out.
    for (int s = 0; s < NSTEPS; s++) {
        int dst_is_out = ((NSTEPS - 1 - s) % 2) == 0;   // last step -> out
        int src_is_scratch, dst_is_scratch;
        const float* src_ext;
        float* dst_ext;
        if (s == 0) { src_ext = T; src_is_scratch = 0; }
        else {
            // src of step s == dst of step s-1
            int prev_dst_is_out = ((NSTEPS - s) % 2) == 0;
            if (prev_dst_is_out) { src_ext = out; src_is_scratch = 0; }
            else                 { src_ext = nullptr; src_is_scratch = 1; }
        }
        if (dst_is_out) { dst_ext = out; dst_is_scratch = 0; }
        else            { dst_ext = nullptr; dst_is_scratch = 1; }

        step_kernel<<<grid, block>>>(src_ext, src_is_scratch,
                                     dst_ext, dst_is_scratch,
                                     ug, vg, mask, H, W);
    }
}

// round 10
// speedup vs baseline: 1.1679x; 1.1679x over previous
#include <cuda_runtime.h>
#include <cuda_bf16.h>

#define R_EARTH  6371000.0f
#define DEG2RADF 0.017453292519943295f
#define DT_SEC   600.0f
#define NSTEPS   48

#define TILE 32

// Scratch ping-pong buffer (B*H*W = 8*1024*1024 floats = 32 MB) — static device
// global, NOT an allocation. 16B-aligned for float4 access.
__device__ __align__(16) float g_scratch[8u * 1024u * 1024u];

// Per-row reciprocal dx terms (H <= 4096) + dy scalars.
__device__ float g_inv_dx[4096];
__device__ float g_inv_2dx[4096];
__device__ float g_inv_dy;
__device__ float g_inv_2dy;

__global__ void setup_kernel(const float* __restrict__ lat,
                             const float* __restrict__ lon, int H) {
    float dlat = lat[1] - lat[0];
    float dlon = lon[1] - lon[0];
    float dy = R_EARTH * DEG2RADF * dlat;
    if (blockIdx.x == 0 && threadIdx.x == 0) {
        g_inv_dy  = 1.0f / dy;
        g_inv_2dy = 0.5f / dy;
    }
    float dx0 = R_EARTH * DEG2RADF * dlon;
    for (int i = blockIdx.x * blockDim.x + threadIdx.x; i < H;
         i += gridDim.x * blockDim.x) {
        float dx = dx0 * cosf(lat[i] * DEG2RADF);
        g_inv_dx[i]  = 1.0f / dx;
        g_inv_2dx[i] = 0.5f / dx;
    }
}

// Shared-memory layout (one struct, ~15.5 KB):
//   sT[r][lx] holds T(gy0-2+r, gx0-4+lx)   for the interior fast path;
//             the generic path fills only lx in [2,37] (cols gx0-2..gx0+33).
//             Consumers read only lx in [2,37].
//   sA[ay][ax] = advected field at (gy0-1+ay, gx0-1+ax)
//   sM[ay][ax] = mask           at (gy0-1+ay, gx0-1+ax)   (0 outside domain)
struct Smem {
    float sT[36][40];
    float sA[34][36];
    float sM[34][36];
};

__device__ __forceinline__ float advect_point(
    const Smem& s, const float* __restrict__ ugb, const float* __restrict__ vgb,
    int ay, int ax, int rowbase, float i2dy, float i2dx) {
    const int lx = ax + 3;
    const int ly = ay + 1;
    float c    = s.sT[ly][lx];
    float dTdy = (s.sT[ly + 1][lx] - s.sT[ly - 1][lx]) * i2dy;
    float dTdx = (s.sT[ly][lx + 1] - s.sT[ly][lx - 1]) * i2dx;
    float adv  = fmaf(ugb[rowbase + ax], dTdx, vgb[rowbase + ax] * dTdy);
    return fmaf(-DT_SEC * s.sM[ay][ax], adv, c);
}

__global__ __launch_bounds__(256, 8)
void step_kernel(const float* __restrict__ src_ext, int src_is_scratch,
                 float* __restrict__ dst_ext, int dst_is_scratch,
                 const float* __restrict__ ug, const float* __restrict__ vg,
                 const float* __restrict__ mask, int H, int W) {
    const float* __restrict__ src = src_is_scratch ? g_scratch : src_ext;
    float* __restrict__       dst = dst_is_scratch ? g_scratch : dst_ext;

    __shared__ Smem s;

    const int b   = blockIdx.z;
    const int gy0 = blockIdx.y * TILE;
    const int gx0 = blockIdx.x * TILE;
    const int plane = H * W;                      // 32-bit: 8M elems max here
    const float* __restrict__ Tb  = src + b * plane;
    const float* __restrict__ ugb = ug  + b * plane;
    const float* __restrict__ vgb = vg  + b * plane;

    const int tx  = threadIdx.x;                  // blockDim = (32, 8)
    const int ty  = threadIdx.y;
    const int tid = ty * 32 + tx;

    // Interior: full halo in-domain, no domain-edge derivative cases,
    // float4-aligned load window.
    const bool interior = (gx0 >= 4) && (gx0 + 36 <= W) &&
                          (gy0 >= 2) && (gy0 + 34 <= H) && ((W & 3) == 0);

    if (interior) {
        // ---- Phase 1a: T halo tile via float4 (36 rows x 10 float4) ----
        #pragma unroll
        for (int i = tid; i < 360; i += 256) {
            int r = i / 10, c = i - r * 10;
            float4 v = *reinterpret_cast<const float4*>(
                Tb + (gy0 - 2 + r) * W + (gx0 - 4) + c * 4);
            *reinterpret_cast<float4*>(&s.sT[r][c * 4]) = v;
        }
        // ---- Phase 1b: mask tile (34 x 34) ----
        #pragma unroll
        for (int k = 0; k < 5; k++) {
            int ay = ty + 8 * k;
            if (ay < 34) {
                const float* mrow = mask + (gy0 - 1 + ay) * W + (gx0 - 1);
                s.sM[ay][tx] = mrow[tx];
                if (tx < 2) s.sM[ay][32 + tx] = mrow[32 + tx];
            }
        }
        __syncthreads();

        // ---- Phase 2: advected field A on 34 x 34 ----
        const float i2dy = g_inv_2dy;
        #pragma unroll
        for (int k = 0; k < 5; k++) {
            int ay = ty + 8 * k;
            if (ay < 34) {
                int gy = gy0 - 1 + ay;
                float i2dx = g_inv_2dx[gy];        // uniform per warp-row
                int rowbase = gy * W + gx0 - 1;
                s.sA[ay][tx] = advect_point(s, ugb, vgb, ay, tx, rowbase, i2dy, i2dx);
                if (tx < 2)
                    s.sA[ay][32 + tx] =
                        advect_point(s, ugb, vgb, ay, 32 + tx, rowbase, i2dy, i2dx);
            }
        }
        __syncthreads();

        // ---- Phase 3: separable 3x3 binomial in registers, 4 rows/thread ----
        {
            const int r0 = ty * 4;
            float hs[6];
            #pragma unroll
            for (int i = 0; i < 6; i++)
                hs[i] = s.sA[r0 + i][tx] + 2.0f * s.sA[r0 + i][tx + 1]
                      + s.sA[r0 + i][tx + 2];
            int obase = (b * H + gy0 + r0) * W + gx0 + tx;
            #pragma unroll
            for (int j = 0; j < 4; j++) {
                float v = (hs[j] + 2.0f * hs[j + 1] + hs[j + 2]) * 0.0625f;
                dst[obase + j * W] = v * s.sM[r0 + j + 1][tx + 1];
            }
        }
        return;
    }

    // ================= Generic (edge) path =================
    // ---- Phase 1: T halo (logical 36x36 at lx offset +2), zero-fill OOB ----
    for (int i = tid; i < 36 * 36; i += 256) {
        int r = i / 36, j = i - r * 36;
        int gy = gy0 - 2 + r, gx = gx0 - 2 + j;
        float v = 0.0f;
        if (gy >= 0 && gy < H && gx >= 0 && gx < W) v = Tb[gy * W + gx];
        s.sT[r][j + 2] = v;
    }
    // ---- mask tile, 0 outside domain ----
    for (int i = tid; i < 34 * 34; i += 256) {
        int ay = i / 34, ax = i - ay * 34;
        int gy = gy0 - 1 + ay, gx = gx0 - 1 + ax;
        float m = 0.0f;
        if (gy >= 0 && gy < H && gx >= 0 && gx < W) m = mask[gy * W + gx];
        s.sM[ay][ax] = m;
    }
    __syncthreads();

    // ---- Phase 2: advection with one-sided derivatives at domain edges ----
    const float inv_dy  = g_inv_dy;
    const float inv_2dy = g_inv_2dy;
    for (int i = tid; i < 34 * 34; i += 256) {
        int ay = i / 34, ax = i - ay * 34;
        int gy = gy0 - 1 + ay, gx = gx0 - 1 + ax;
        float a = 0.0f;
        if (gy >= 0 && gy < H && gx >= 0 && gx < W) {
            int lx = ax + 3, lyc = ay + 1;
            float c = s.sT[lyc][lx];
            float dTdy;
            if (gy == 0)          dTdy = (s.sT[lyc + 1][lx] - c) * inv_dy;
            else if (gy == H - 1) dTdy = (c - s.sT[lyc - 1][lx]) * inv_dy;
            else                  dTdy = (s.sT[lyc + 1][lx] - s.sT[lyc - 1][lx]) * inv_2dy;
            float dTdx;
            if (gx == 0)          dTdx = (s.sT[lyc][lx + 1] - c) * g_inv_dx[gy];
            else if (gx == W - 1) dTdx = (c - s.sT[lyc][lx - 1]) * g_inv_dx[gy];
            else                  dTdx = (s.sT[lyc][lx + 1] - s.sT[lyc][lx - 1]) * g_inv_2dx[gy];
            int g = gy * W + gx;
            float adv = fmaf(ugb[g], dTdx, vgb[g] * dTdy);
            a = fmaf(-DT_SEC * s.sM[ay][ax], adv, c);
        }
        s.sA[ay][ax] = a;
    }
    __syncthreads();

    // ---- Phase 3: smoothing (A is zero outside domain => zero padding) ----
    {
        const int gx = gx0 + tx;
        if (gx < W) {
            const int r0 = ty * 4;
            float hs[6];
            #pragma unroll
            for (int i = 0; i < 6; i++)
                hs[i] = s.sA[r0 + i][tx] + 2.0f * s.sA[r0 + i][tx + 1]
                      + s.sA[r0 + i][tx + 2];
            #pragma unroll
            for (int j = 0; j < 4; j++) {
                int gy = gy0 + r0 + j;
                if (gy < H) {
                    float v = (hs[j] + 2.0f * hs[j + 1] + hs[j + 2]) * 0.0625f;
                    dst[(b * H + gy) * W + gx] = v * s.sM[r0 + j + 1][tx + 1];
                }
            }
        }
    }
}

extern "C" void kernel_launch(void* const* d_in, const int* in_sizes, int n_in,
                              void* d_out, int out_size) {
    const float* T    = (const float*)d_in[0];
    const float* ug   = (const float*)d_in[1];
    const float* vg   = (const float*)d_in[2];
    const float* lat  = (const float*)d_in[3];
    const float* lon  = (const float*)d_in[4];
    const float* mask = (const float*)d_in[5];
    float* out = (float*)d_out;

    const int H = in_sizes[3];
    const int W = in_sizes[4];
    const int B = in_sizes[0] / (H * W);

    setup_kernel<<<(H + 255) / 256, 256>>>(lat, lon, H);

    dim3 block(32, 8);
    dim3 grid((W + TILE - 1) / TILE, (H + TILE - 1) / TILE, B);

    // Ping-pong so that the final step (s = NSTEPS-1) writes d_out.
    for (int s = 0; s < NSTEPS; s++) {
        int dst_is_out = ((NSTEPS - 1 - s) % 2) == 0;   // last step -> out
        int src_is_scratch, dst_is_scratch;
        const float* src_ext;
        float* dst_ext;
        if (s == 0) { src_ext = T; src_is_scratch = 0; }
        else {
            int prev_dst_is_out = ((NSTEPS - s) % 2) == 0;
            if (prev_dst_is_out) { src_ext = out; src_is_scratch = 0; }
            else                 { src_ext = nullptr; src_is_scratch = 1; }
        }
        if (dst_is_out) { dst_ext = out; dst_is_scratch = 0; }
        else            { dst_ext = nullptr; dst_is_scratch = 1; }

        step_kernel<<<grid, block>>>(src_ext, src_is_scratch,
                                     dst_ext, dst_is_scratch,
                                     ug, vg, mask, H, W);
    }
}